// round 1
// baseline (speedup 1.0000x reference)
#include <cuda_runtime.h>

// Problem constants (fixed shapes from the reference)
#define NE      513          // NUM_EDGES + 1
#define LHOPS   5
#define HEADS   8
#define FEAT    64
#define NPAIRS  (8*128*128)  // B*N*N = 131072
#define PROJ_ELEMS (LHOPS*NE*HEADS)  // 20520 floats = 82080 bytes

// Scratch for the precomputed projection table proj[l][e][h]
__device__ __align__(16) float g_proj[PROJ_ELEMS];

// Kernel A: proj[l][e][h] = sum_f edge_emb[e][f] * attn_w[l][f][h]
// One thread per (l,e,h) output; 8 consecutive threads share the same emb row
// (broadcast in L1) and read consecutive attn_w words (coalesced).
__global__ void proj_kernel(const float* __restrict__ emb,
                            const float* __restrict__ w) {
    int gid = blockIdx.x * blockDim.x + threadIdx.x;
    if (gid >= PROJ_ELEMS) return;
    int h   = gid & (HEADS - 1);
    int row = gid >> 3;              // l*NE + e
    int l   = row / NE;
    int e   = row - l * NE;
    const float* er = emb + e * FEAT;
    const float* wr = w + l * FEAT * HEADS + h;
    float acc = 0.f;
    #pragma unroll
    for (int f = 0; f < FEAT; ++f)
        acc = fmaf(er[f], wr[f * HEADS], acc);
    g_proj[gid] = acc;
}

// Kernel B: stage proj table into smem, then stream (b,x,y) pairs:
//   out[pair][h] = (0.5/dist[pair]) * sum_{l,d} proj[l][path_data[pair][l][d]][h]
// Handles both int64 and int32 index/dist dtypes (runtime-detected).
__global__ void __launch_bounds__(512) enc_kernel(const void* __restrict__ distp,
                                                  const void* __restrict__ pdp,
                                                  float* __restrict__ out) {
    extern __shared__ float s_proj[];
    // cooperative vectorized table load (20520 floats = 5130 float4)
    {
        const float4* gsrc = (const float4*)g_proj;
        float4* sdst = (float4*)s_proj;
        for (int i = threadIdx.x; i < PROJ_ELEMS / 4; i += blockDim.x)
            sdst[i] = gsrc[i];
    }
    __syncthreads();

    // dtype detection: dist values are in [1,5]. If stored as int64 (LE),
    // int32 word #1 is the high half of dist[0] == 0. If int32, it's
    // dist[1] in [1,5] != 0.
    const bool is64 = (((const int*)distp)[1] == 0);

    const int stride = gridDim.x * blockDim.x;
    for (int pair = blockIdx.x * blockDim.x + threadIdx.x; pair < NPAIRS;
         pair += stride) {
        int idx[2 * LHOPS];
        float scale;
        if (is64) {
            // 10 int64 = 80 bytes contiguous, always 16B-aligned (80 = 5*16)
            const int4* p =
                (const int4*)((const long long*)pdp + (size_t)pair * 10);
            #pragma unroll
            for (int j = 0; j < 5; ++j) {
                int4 v = p[j];           // two int64: low words are .x and .z
                idx[2 * j]     = v.x;
                idx[2 * j + 1] = v.z;
            }
            scale = 0.5f / (float)((const long long*)distp)[pair];
        } else {
            // 10 int32 = 40 bytes contiguous, always 8B-aligned
            const int2* p = (const int2*)((const int*)pdp + (size_t)pair * 10);
            #pragma unroll
            for (int j = 0; j < 5; ++j) {
                int2 v = p[j];
                idx[2 * j]     = v.x;
                idx[2 * j + 1] = v.y;
            }
            scale = 0.5f / (float)((const int*)distp)[pair];
        }

        float4 a0 = make_float4(0.f, 0.f, 0.f, 0.f);
        float4 a1 = make_float4(0.f, 0.f, 0.f, 0.f);
        #pragma unroll
        for (int j = 0; j < 2 * LHOPS; ++j) {
            int l = j >> 1;  // path_data layout [...,L,D]: j = l*2 + d
            const float4* row =
                (const float4*)(s_proj + (size_t)(l * NE + idx[j]) * HEADS);
            float4 r0 = row[0];
            float4 r1 = row[1];
            a0.x += r0.x; a0.y += r0.y; a0.z += r0.z; a0.w += r0.w;
            a1.x += r1.x; a1.y += r1.y; a1.z += r1.z; a1.w += r1.w;
        }

        float4* o = (float4*)(out + (size_t)pair * HEADS);
        o[0] = make_float4(a0.x * scale, a0.y * scale, a0.z * scale, a0.w * scale);
        o[1] = make_float4(a1.x * scale, a1.y * scale, a1.z * scale, a1.w * scale);
    }
}

extern "C" void kernel_launch(void* const* d_in, const int* in_sizes, int n_in,
                              void* d_out, int out_size) {
    const void*  dist = d_in[0];
    const void*  pd   = d_in[1];
    const float* emb  = (const float*)d_in[2];
    const float* w    = (const float*)d_in[3];

    // 82 KB dynamic smem opt-in (idempotent; unconditional — no static guards)
    cudaFuncSetAttribute(enc_kernel,
                         cudaFuncAttributeMaxDynamicSharedMemorySize,
                         PROJ_ELEMS * (int)sizeof(float));

    proj_kernel<<<(PROJ_ELEMS + 255) / 256, 256>>>(emb, w);
    enc_kernel<<<148, 512, PROJ_ELEMS * (int)sizeof(float)>>>(
        dist, pd, (float*)d_out);
}